// round 15
// baseline (speedup 1.0000x reference)
#include <cuda_runtime.h>
#include <cuda_bf16.h>
#include <cstdint>
#include <cstddef>

// ---------------------------------------------------------------------------
// Problem constants
// ---------------------------------------------------------------------------
#define N_CODES 4880
#define T_STEPS 4096
#define VDIM    512
#define HD      512
#define G3      1536   // 3*HD
#define KPAD    4896   // 153*32 = 306*16 (zero-padded beyond 4880)

typedef unsigned long long ull;

// ---------------------------------------------------------------------------
// Scratch (device globals — no allocation allowed)
// ---------------------------------------------------------------------------
__device__ float g_visit[(size_t)T_STEPS * VDIM];     // 8 MB
__device__ float g_gi[(size_t)T_STEPS * G3];          // 24 MB
__device__ float g_hs[(size_t)T_STEPS * HD];          // 8 MB
__device__ float g_logits[T_STEPS];
__device__ float g_alpha[T_STEPS];
__device__ float g_part[128 * HD];
__device__ __nv_bfloat16 g_HhiT[(size_t)T_STEPS * KPAD];  // H.T hi
__device__ __nv_bfloat16 g_HloT[(size_t)T_STEPS * KPAD];  // H.T lo
__device__ __nv_bfloat16 g_XhiT[(size_t)VDIM * KPAD];     // X.T hi
__device__ __nv_bfloat16 g_XloT[(size_t)VDIM * KPAD];     // X.T lo

// ---------------------------------------------------------------------------
// Helpers
// ---------------------------------------------------------------------------
__device__ __forceinline__ unsigned smem_u32(const void* p) {
    unsigned a;
    asm("{ .reg .u64 t; cvta.to.shared.u64 t, %1; cvt.u32.u64 %0, t; }"
        : "=r"(a) : "l"(p));
    return a;
}
__device__ __forceinline__ unsigned mapa_u32(unsigned laddr, int rk) {
    unsigned r;
    asm("mapa.shared::cluster.u32 %0, %1, %2;" : "=r"(r) : "r"(laddr), "r"(rk));
    return r;
}
__device__ __forceinline__ ull pk2(float a, float b) {
    ull r; asm("mov.b64 %0, {%1, %2};" : "=l"(r) : "f"(a), "f"(b)); return r;
}
__device__ __forceinline__ ull pk2dup(float a) { return pk2(a, a); }
__device__ __forceinline__ void fma2(ull& d, ull a, ull b) {
    asm("fma.rn.f32x2 %0, %1, %2, %0;" : "+l"(d) : "l"(a), "l"(b));
}
__device__ __forceinline__ float2 upk2(ull v) {
    float2 r; asm("mov.b64 {%0, %1}, %2;" : "=f"(r.x), "=f"(r.y) : "l"(v));
    return r;
}
__device__ __forceinline__ float tanh_fast(float x) {
    float r; asm("tanh.approx.f32 %0, %1;" : "=f"(r) : "f"(x)); return r;
}
__device__ __forceinline__ void cluster_sync_all() {
    asm volatile("barrier.cluster.arrive.aligned;" ::: "memory");
    asm volatile("barrier.cluster.wait.aligned;" ::: "memory");
}
__device__ __forceinline__ void mbar_init(unsigned a, unsigned cnt) {
    asm volatile("mbarrier.init.shared.b64 [%0], %1;" :: "r"(a), "r"(cnt) : "memory");
}
__device__ __forceinline__ void mbar_expect(unsigned a, unsigned bytes) {
    asm volatile("mbarrier.arrive.expect_tx.shared.b64 _, [%0], %1;"
                 :: "r"(a), "r"(bytes) : "memory");
}
__device__ __forceinline__ void mbar_wait(unsigned a, unsigned parity) {
    asm volatile(
        "{\n\t.reg .pred P;\n\t"
        "LW_%=:\n\t"
        "mbarrier.try_wait.parity.acquire.cluster.shared::cta.b64 P, [%0], %1, 0x989680;\n\t"
        "@P bra.uni LD_%=;\n\t"
        "bra.uni LW_%=;\n\t"
        "LD_%=:\n\t}"
        :: "r"(a), "r"(parity) : "memory");
}
__device__ __forceinline__ void st_async_pre(unsigned ra, unsigned rb, unsigned val) {
    asm volatile(
        "st.async.shared::cluster.mbarrier::complete_tx::bytes.b32 [%0], %1, [%2];"
        :: "r"(ra), "r"(val), "r"(rb) : "memory");
}

// bf16 warp MMA: D(16x8,f32) += A(16x16,bf16) * B(16x8,bf16)
__device__ __forceinline__ void mma_bf16(float c[4], const unsigned a[4],
                                         unsigned b0, unsigned b1) {
    asm volatile(
        "mma.sync.aligned.m16n8k16.row.col.f32.bf16.bf16.f32 "
        "{%0,%1,%2,%3}, {%4,%5,%6,%7}, {%8,%9}, {%0,%1,%2,%3};"
        : "+f"(c[0]), "+f"(c[1]), "+f"(c[2]), "+f"(c[3])
        : "r"(a[0]), "r"(a[1]), "r"(a[2]), "r"(a[3]), "r"(b0), "r"(b1));
}

// ---------------------------------------------------------------------------
// Transpose + bf16 hi/lo split conversion:  src[K][N] -> dst[N][KPAD] (zero pad)
// ---------------------------------------------------------------------------
__device__ __forceinline__ void convert_body(const float* __restrict__ src,
                                             __nv_bfloat16* __restrict__ dhi,
                                             __nv_bfloat16* __restrict__ dlo,
                                             int K, int N)
{
    __shared__ float tile[32][33];
    int x = threadIdx.x & 31, y = threadIdx.x >> 5;      // 32 x 8
    int k0 = blockIdx.x * 32, n0 = blockIdx.y * 32;
#pragma unroll
    for (int j = 0; j < 4; j++) {
        int k = k0 + y + j * 8;
        float v = 0.f;
        if (k < K) v = src[(size_t)k * N + n0 + x];
        tile[y + j * 8][x] = v;
    }
    __syncthreads();
#pragma unroll
    for (int j = 0; j < 4; j++) {
        int n = n0 + y + j * 8;
        int k = k0 + x;
        float v = tile[x][y + j * 8];
        __nv_bfloat16 hi = __float2bfloat16(v);
        float r = v - __bfloat162float(hi);
        __nv_bfloat16 lo = __float2bfloat16(r);
        dhi[(size_t)n * KPAD + k] = hi;
        dlo[(size_t)n * KPAD + k] = lo;
    }
}
__global__ void __launch_bounds__(256)
convert_H_kernel(const float* __restrict__ H)
{ convert_body(H, g_HhiT, g_HloT, N_CODES, T_STEPS); }
__global__ void __launch_bounds__(256)
convert_X_kernel(const float* __restrict__ X)
{ convert_body(X, g_XhiT, g_XloT, N_CODES, VDIM); }

// ---------------------------------------------------------------------------
// GEMM1 via mma.sync bf16, split-bf16 3 terms.
//   CTA 128x64 output, 8 warps each 32x32 (2 m-tiles x 4 n-tiles).
//   Fragments loaded straight from global (k-contiguous pairs, 4B aligned).
// ---------------------------------------------------------------------------
__global__ void __launch_bounds__(256)
gemm1_mma_kernel()
{
    const int tid  = threadIdx.x;
    const int w    = tid >> 5;
    const int lane = tid & 31;
    const int gid  = lane >> 2;       // 0..7
    const int tq   = lane & 3;        // 0..3

    const int m0 = blockIdx.x * 128 + (w & 3) * 32;   // warp's first m-row
    const int n0 = blockIdx.y * 64 + (w >> 2) * 32;   // warp's first n-col

    float acc[2][4][4];
#pragma unroll
    for (int mt = 0; mt < 2; mt++)
#pragma unroll
        for (int nt = 0; nt < 4; nt++)
#pragma unroll
            for (int i = 0; i < 4; i++) acc[mt][nt][i] = 0.0f;

    const __nv_bfloat16* Ahi0 = g_HhiT + (size_t)(m0 + gid) * KPAD + 2 * tq;
    const __nv_bfloat16* Alo0 = g_HloT + (size_t)(m0 + gid) * KPAD + 2 * tq;
    const __nv_bfloat16* Bhi0 = g_XhiT + (size_t)(n0 + gid) * KPAD + 2 * tq;
    const __nv_bfloat16* Blo0 = g_XloT + (size_t)(n0 + gid) * KPAD + 2 * tq;

    for (int k = 0; k < KPAD; k += 16) {
        unsigned ahi[2][4], alo[2][4];
#pragma unroll
        for (int mt = 0; mt < 2; mt++) {
            const size_t r = (size_t)(mt * 16) * KPAD + k;
            ahi[mt][0] = __ldg((const unsigned*)(Ahi0 + r));
            ahi[mt][1] = __ldg((const unsigned*)(Ahi0 + r + 8 * KPAD));
            ahi[mt][2] = __ldg((const unsigned*)(Ahi0 + r + 8));
            ahi[mt][3] = __ldg((const unsigned*)(Ahi0 + r + 8 * KPAD + 8));
            alo[mt][0] = __ldg((const unsigned*)(Alo0 + r));
            alo[mt][1] = __ldg((const unsigned*)(Alo0 + r + 8 * KPAD));
            alo[mt][2] = __ldg((const unsigned*)(Alo0 + r + 8));
            alo[mt][3] = __ldg((const unsigned*)(Alo0 + r + 8 * KPAD + 8));
        }
#pragma unroll
        for (int nt = 0; nt < 4; nt++) {
            const size_t c = (size_t)(nt * 8) * KPAD + k;
            unsigned bh0 = __ldg((const unsigned*)(Bhi0 + c));
            unsigned bh1 = __ldg((const unsigned*)(Bhi0 + c + 8));
            unsigned bl0 = __ldg((const unsigned*)(Blo0 + c));
            unsigned bl1 = __ldg((const unsigned*)(Blo0 + c + 8));
#pragma unroll
            for (int mt = 0; mt < 2; mt++) {
                mma_bf16(acc[mt][nt], ahi[mt], bh0, bh1);
                mma_bf16(acc[mt][nt], ahi[mt], bl0, bl1);
                mma_bf16(acc[mt][nt], alo[mt], bh0, bh1);
            }
        }
    }

    // store: c0,c1 -> (row, col..col+1); c2,c3 -> (row+8, col..col+1)
#pragma unroll
    for (int mt = 0; mt < 2; mt++) {
        int row = m0 + mt * 16 + gid;
#pragma unroll
        for (int nt = 0; nt < 4; nt++) {
            int col = n0 + nt * 8 + 2 * tq;
            *(float2*)(g_visit + (size_t)row * VDIM + col) =
                make_float2(acc[mt][nt][0], acc[mt][nt][1]);
            *(float2*)(g_visit + (size_t)(row + 8) * VDIM + col) =
                make_float2(acc[mt][nt][2], acc[mt][nt][3]);
        }
    }
}

// ---------------------------------------------------------------------------
// GEMM2: gi[t][g] = b_ih[g] + sum_d visit[t][d] * W_ih[g][d]
//   Register-staged double buffer (R13, validated).
// ---------------------------------------------------------------------------
__global__ void __launch_bounds__(256)
gemm2_kernel(const float* __restrict__ Wih, const float* __restrict__ bih)
{
    __shared__ float As[16 * 128];
    __shared__ float Bs[16 * 64];
    const int tid = threadIdx.x;
    const int t0 = blockIdx.x * 128;
    const int g0 = blockIdx.y * 64;
    const int tx = tid & 15;
    const int ty = tid >> 4;

    const int s_tt0 = tid >> 2;
    const int s_kk  = (tid & 3) << 2;
    const int s_gg  = tid >> 2;

    ull acc2[4][4];
#pragma unroll
    for (int mp = 0; mp < 4; mp++)
#pragma unroll
        for (int n = 0; n < 4; n++) acc2[mp][n] = 0ull;

    float4 ra0, ra1, rbv;
    auto load_tile = [&](int k0) {
        ra0 = *(const float4*)(g_visit + (size_t)(t0 + s_tt0) * VDIM + k0 + s_kk);
        ra1 = *(const float4*)(g_visit + (size_t)(t0 + s_tt0 + 64) * VDIM + k0 + s_kk);
        rbv = *(const float4*)(Wih + (size_t)(g0 + s_gg) * VDIM + k0 + s_kk);
    };
    auto store_tile = [&]() {
        As[(s_kk + 0) * 128 + s_tt0] = ra0.x;
        As[(s_kk + 1) * 128 + s_tt0] = ra0.y;
        As[(s_kk + 2) * 128 + s_tt0] = ra0.z;
        As[(s_kk + 3) * 128 + s_tt0] = ra0.w;
        As[(s_kk + 0) * 128 + s_tt0 + 64] = ra1.x;
        As[(s_kk + 1) * 128 + s_tt0 + 64] = ra1.y;
        As[(s_kk + 2) * 128 + s_tt0 + 64] = ra1.z;
        As[(s_kk + 3) * 128 + s_tt0 + 64] = ra1.w;
        Bs[(s_kk + 0) * 64 + s_gg] = rbv.x;
        Bs[(s_kk + 1) * 64 + s_gg] = rbv.y;
        Bs[(s_kk + 2) * 64 + s_gg] = rbv.z;
        Bs[(s_kk + 3) * 64 + s_gg] = rbv.w;
    };

    load_tile(0);
    for (int k0 = 0; k0 < VDIM; k0 += 16) {
        store_tile();
        __syncthreads();
        if (k0 + 16 < VDIM) load_tile(k0 + 16);
#pragma unroll
        for (int kk = 0; kk < 16; kk++) {
            const longlong2* ap = (const longlong2*)(As + (kk << 7) + (ty << 3));
            longlong2 a01 = ap[0];
            longlong2 a23 = ap[1];
            ull am[4] = {(ull)a01.x, (ull)a01.y, (ull)a23.x, (ull)a23.y};
            float4 b = *(const float4*)(Bs + (kk << 6) + (tx << 2));
            ull bd[4] = {pk2dup(b.x), pk2dup(b.y), pk2dup(b.z), pk2dup(b.w)};
#pragma unroll
            for (int mp = 0; mp < 4; mp++)
#pragma unroll
                for (int n = 0; n < 4; n++)
                    fma2(acc2[mp][n], am[mp], bd[n]);
        }
        __syncthreads();
    }
    float4 bv = *(const float4*)(bih + g0 + (tx << 2));
#pragma unroll
    for (int mp = 0; mp < 4; mp++) {
        float2 c0 = upk2(acc2[mp][0]);
        float2 c1 = upk2(acc2[mp][1]);
        float2 c2 = upk2(acc2[mp][2]);
        float2 c3 = upk2(acc2[mp][3]);
        size_t r0 = (size_t)(t0 + (ty << 3) + 2 * mp) * G3 + g0 + (tx << 2);
        *(float4*)(g_gi + r0)      = make_float4(c0.x + bv.x, c1.x + bv.y, c2.x + bv.z, c3.x + bv.w);
        *(float4*)(g_gi + r0 + G3) = make_float4(c0.y + bv.x, c1.y + bv.y, c2.y + bv.z, c3.y + bv.w);
    }
}

// ---------------------------------------------------------------------------
// GRU scan — frozen R10 build (best validated).
// ---------------------------------------------------------------------------
#define SCAN_THREADS 256

__global__ void __launch_bounds__(SCAN_THREADS, 1)
scan_kernel(const float* __restrict__ Whh, const float* __restrict__ bhh)
{
    __shared__ float  hT[2 * HD];
    __shared__ ull    mbar[2];

    const int tid  = threadIdx.x;
    const int lane = tid & 31;
    const int w    = tid >> 5;
    const int cta  = blockIdx.x;
    const int c4   = lane & 15;
    const int rh   = lane >> 4;

    const int ui    = ((lane & 1) << 1) | rh;
    const int q     = (lane >> 1) & 7;
    const int ul    = (w << 2) + ui;
    const int u_gbl = (cta << 5) + ul;

    ull wreg[6][16];
#pragma unroll
    for (int g = 0; g < 6; g++) {
        int grow = ((g >> 1) << 9) + (cta << 5) + (w << 2) + ((g & 1) << 1) + rh;
        const ull* src = (const ull*)(Whh + (size_t)grow * HD + (c4 << 5));
#pragma unroll
        for (int k = 0; k < 16; k++) wreg[g][k] = src[k];
    }
    const float br = bhh[u_gbl];
    const float bz = bhh[HD + u_gbl];
    const float bn = bhh[2 * HD + u_gbl];

    for (int i = tid; i < HD; i += SCAN_THREADS) hT[i] = 0.0f;
    if (tid == 0) { mbar_init(smem_u32(&mbar[0]), 1); mbar_init(smem_u32(&mbar[1]), 1); }
    __syncthreads();
    cluster_sync_all();

    const int hoffb = ((ul >> 2) << 6) + (cta << 2) + (ul & 3);
    unsigned rdata[2][2], rbar[2][2];
#pragma unroll
    for (int b = 0; b < 2; b++) {
        unsigned ld = smem_u32(&hT[(b << 9) + hoffb]);
        unsigned lm = smem_u32(&mbar[b]);
#pragma unroll
        for (int r = 0; r < 2; r++) {
            rdata[b][r] = mapa_u32(ld, (q << 1) + r);
            rbar[b][r]  = mapa_u32(lm, (q << 1) + r);
        }
    }

    const float* gp_cur = g_gi + u_gbl;
    float gir = __ldg(gp_cur);
    float giz = __ldg(gp_cur + HD);
    float gin = __ldg(gp_cur + 2 * HD);

    int ph0 = 0, ph1 = 0;
    const bool b0 = (lane & 1);
    for (int t = 0; t < T_STEPS; t++) {
        const int cb = t & 1;
        const int nb = cb ^ 1;

        if (tid == 0) mbar_expect(smem_u32(&mbar[nb]), 2048u);

        const float* gp_n = (t + 1 < T_STEPS) ? (gp_cur + G3) : gp_cur;
        float girn = __ldg(gp_n);
        float gizn = __ldg(gp_n + HD);
        float ginn = __ldg(gp_n + 2 * HD);
        gp_cur = gp_n;

        ull h2[16];
        {
            const longlong2* hp = (const longlong2*)(hT + (cb << 9));
#pragma unroll
            for (int j = 0; j < 8; j++) {
                longlong2 qv = hp[(j << 4) + c4];
                h2[2 * j]     = (ull)qv.x;
                h2[2 * j + 1] = (ull)qv.y;
            }
        }
        float hold = hT[(cb << 9) + hoffb];

        float accs[6];
#pragma unroll
        for (int g = 0; g < 6; g++) {
            ull a = 0ull;
#pragma unroll
            for (int k = 0; k < 16; k++) fma2(a, wreg[g][k], h2[k]);
            float2 u2 = upk2(a);
            accs[g] = u2.x + u2.y;
        }

#pragma unroll
        for (int d = 8; d > 1; d >>= 1)
#pragma unroll
            for (int g = 0; g < 6; g++)
                accs[g] += __shfl_xor_sync(0xffffffffu, accs[g], d);

        float v0 = b0 ? accs[0] : accs[1];
        float v1 = b0 ? accs[2] : accs[3];
        float v2 = b0 ? accs[4] : accs[5];
        float pr = (b0 ? accs[1] : accs[0]) + __shfl_xor_sync(0xffffffffu, v0, 1);
        float pz = (b0 ? accs[3] : accs[2]) + __shfl_xor_sync(0xffffffffu, v1, 1);
        float pn = (b0 ? accs[5] : accs[4]) + __shfl_xor_sync(0xffffffffu, v2, 1);

        float rg = fmaf(0.5f, tanh_fast(0.5f * (gir + pr + br)), 0.5f);
        float zg = fmaf(0.5f, tanh_fast(0.5f * (giz + pz + bz)), 0.5f);
        float ng = tanh_fast(fmaf(rg, pn + bn, gin));
        float hnew = fmaf(zg, hold - ng, ng);

        if (q == 0) g_hs[(size_t)t * HD + u_gbl] = hnew;

        unsigned hv = __float_as_uint(hnew);
        st_async_pre(rdata[nb][0], rbar[nb][0], hv);
        st_async_pre(rdata[nb][1], rbar[nb][1], hv);

        gir = girn; giz = gizn; gin = ginn;

        unsigned par = nb ? (unsigned)ph1 : (unsigned)ph0;
        mbar_wait(smem_u32(&mbar[nb]), par);
        if (nb) ph1 ^= 1; else ph0 ^= 1;
    }
    cluster_sync_all();
}

// ---------------------------------------------------------------------------
// Attention pooling (R13, validated)
// ---------------------------------------------------------------------------
__global__ void __launch_bounds__(256)
att_logits_kernel(const float* __restrict__ watt)
{
    int t = blockIdx.x * 8 + (threadIdx.x >> 5);
    int lane = threadIdx.x & 31;
    const float4* hp = (const float4*)(g_hs + (size_t)t * HD);
    const float4* wp = (const float4*)watt;
    float acc = 0.f;
#pragma unroll
    for (int j = 0; j < 4; j++) {
        float4 h4 = __ldg(hp + lane + (j << 5));
        float4 w4 = __ldg(wp + lane + (j << 5));
        acc += h4.x * w4.x + h4.y * w4.y + h4.z * w4.z + h4.w * w4.w;
    }
    acc += __shfl_xor_sync(0xffffffffu, acc, 16);
    acc += __shfl_xor_sync(0xffffffffu, acc, 8);
    acc += __shfl_xor_sync(0xffffffffu, acc, 4);
    acc += __shfl_xor_sync(0xffffffffu, acc, 2);
    acc += __shfl_xor_sync(0xffffffffu, acc, 1);
    if (lane == 0) g_logits[t] = acc;
}

__global__ void __launch_bounds__(1024)
att_softmax_kernel()
{
    __shared__ float red[1024];
    int tid = threadIdx.x;
    float l[4];
    float mx = -1e30f;
#pragma unroll
    for (int i = 0; i < 4; i++) {
        l[i] = g_logits[tid + (i << 10)];
        mx = fmaxf(mx, l[i]);
    }
    red[tid] = mx;
    __syncthreads();
    for (int s = 512; s > 0; s >>= 1) {
        if (tid < s) red[tid] = fmaxf(red[tid], red[tid + s]);
        __syncthreads();
    }
    mx = red[0];
    __syncthreads();
    float e[4];
    float se = 0.f;
#pragma unroll
    for (int i = 0; i < 4; i++) {
        e[i] = __expf(l[i] - mx);
        se += e[i];
    }
    red[tid] = se;
    __syncthreads();
    for (int s = 512; s > 0; s >>= 1) {
        if (tid < s) red[tid] += red[tid + s];
        __syncthreads();
    }
    float inv = 1.0f / red[0];
#pragma unroll
    for (int i = 0; i < 4; i++)
        g_alpha[tid + (i << 10)] = e[i] * inv;
}

__global__ void __launch_bounds__(512)
att_out_kernel()
{
    int b = blockIdx.x;
    int d = threadIdx.x;
    float acc = 0.f;
#pragma unroll 4
    for (int i = 0; i < 32; i++) {
        int t = b * 32 + i;
        acc += g_alpha[t] * g_hs[(size_t)t * HD + d];
    }
    g_part[b * HD + d] = acc;
}

__global__ void __launch_bounds__(512)
att_final_kernel(float* __restrict__ out)
{
    int d = threadIdx.x;
    float acc = 0.f;
#pragma unroll
    for (int b = 0; b < 128; b++)
        acc += g_part[b * HD + d];
    out[d] = acc;
}

// ---------------------------------------------------------------------------
// Launch — single stream (proven structure)
// ---------------------------------------------------------------------------
extern "C" void kernel_launch(void* const* d_in, const int* in_sizes, int n_in,
                              void* d_out, int out_size)
{
    const float* H    = (const float*)d_in[0];
    // d_in[1] = TE (unused by reference)
    const float* X    = (const float*)d_in[2];
    const float* Wih  = (const float*)d_in[3];
    const float* Whh  = (const float*)d_in[4];
    const float* bih  = (const float*)d_in[5];
    const float* bhh  = (const float*)d_in[6];
    const float* watt = (const float*)d_in[7];
    float* out = (float*)d_out;

    convert_H_kernel<<<dim3(153, 128), 256>>>(H);
    convert_X_kernel<<<dim3(153, 16), 256>>>(X);

    gemm1_mma_kernel<<<dim3(32, 8), 256>>>();

    gemm2_kernel<<<dim3(32, 24), 256>>>(Wih, bih);

    cudaFuncSetAttribute(scan_kernel,
                         cudaFuncAttributeNonPortableClusterSizeAllowed, 1);

    cudaLaunchConfig_t cfg = {};
    cfg.gridDim = dim3(16, 1, 1);
    cfg.blockDim = dim3(SCAN_THREADS, 1, 1);
    cfg.dynamicSmemBytes = 0;
    cfg.stream = 0;
    cudaLaunchAttribute attr[1];
    attr[0].id = cudaLaunchAttributeClusterDimension;
    attr[0].val.clusterDim.x = 16;
    attr[0].val.clusterDim.y = 1;
    attr[0].val.clusterDim.z = 1;
    cfg.attrs = attr;
    cfg.numAttrs = 1;
    cudaLaunchKernelEx(&cfg, scan_kernel, Whh, bhh);

    att_logits_kernel<<<512, 256>>>(watt);
    att_softmax_kernel<<<1, 1024>>>();
    att_out_kernel<<<128, 512>>>();
    att_final_kernel<<<1, 512>>>(out);
}

// round 16
// speedup vs baseline: 1.0787x; 1.0787x over previous
#include <cuda_runtime.h>
#include <cuda_bf16.h>
#include <cstdint>
#include <cstddef>

// ---------------------------------------------------------------------------
// Problem constants
// ---------------------------------------------------------------------------
#define N_CODES 4880
#define T_STEPS 4096
#define VDIM    512
#define HD      512
#define G3      1536   // 3*HD
#define KPAD    4896   // 153*32

typedef unsigned long long ull;

// ---------------------------------------------------------------------------
// Scratch (device globals — no allocation allowed)
// ---------------------------------------------------------------------------
__device__ float g_visit[(size_t)T_STEPS * VDIM];
__device__ float g_gi[(size_t)T_STEPS * G3];
__device__ float g_hs[(size_t)T_STEPS * HD];
__device__ float g_logits[T_STEPS];
__device__ float g_alpha[T_STEPS];
__device__ float g_part[128 * HD];
__device__ __nv_bfloat16 g_HhiT[(size_t)T_STEPS * KPAD];
__device__ __nv_bfloat16 g_HloT[(size_t)T_STEPS * KPAD];
__device__ __nv_bfloat16 g_XhiT[(size_t)VDIM * KPAD];
__device__ __nv_bfloat16 g_XloT[(size_t)VDIM * KPAD];

// ---------------------------------------------------------------------------
// Helpers
// ---------------------------------------------------------------------------
__device__ __forceinline__ unsigned smem_u32(const void* p) {
    unsigned a;
    asm("{ .reg .u64 t; cvta.to.shared.u64 t, %1; cvt.u32.u64 %0, t; }"
        : "=r"(a) : "l"(p));
    return a;
}
__device__ __forceinline__ unsigned mapa_u32(unsigned laddr, int rk) {
    unsigned r;
    asm("mapa.shared::cluster.u32 %0, %1, %2;" : "=r"(r) : "r"(laddr), "r"(rk));
    return r;
}
__device__ __forceinline__ ull pk2(float a, float b) {
    ull r; asm("mov.b64 %0, {%1, %2};" : "=l"(r) : "f"(a), "f"(b)); return r;
}
__device__ __forceinline__ ull pk2dup(float a) { return pk2(a, a); }
__device__ __forceinline__ void fma2(ull& d, ull a, ull b) {
    asm("fma.rn.f32x2 %0, %1, %2, %0;" : "+l"(d) : "l"(a), "l"(b));
}
__device__ __forceinline__ float2 upk2(ull v) {
    float2 r; asm("mov.b64 {%0, %1}, %2;" : "=f"(r.x), "=f"(r.y) : "l"(v));
    return r;
}
__device__ __forceinline__ float tanh_fast(float x) {
    float r; asm("tanh.approx.f32 %0, %1;" : "=f"(r) : "f"(x)); return r;
}
__device__ __forceinline__ void cluster_sync_all() {
    asm volatile("barrier.cluster.arrive.aligned;" ::: "memory");
    asm volatile("barrier.cluster.wait.aligned;" ::: "memory");
}
__device__ __forceinline__ void mbar_init(unsigned a, unsigned cnt) {
    asm volatile("mbarrier.init.shared.b64 [%0], %1;" :: "r"(a), "r"(cnt) : "memory");
}
__device__ __forceinline__ void mbar_expect(unsigned a, unsigned bytes) {
    asm volatile("mbarrier.arrive.expect_tx.shared.b64 _, [%0], %1;"
                 :: "r"(a), "r"(bytes) : "memory");
}
__device__ __forceinline__ void mbar_wait(unsigned a, unsigned parity) {
    asm volatile(
        "{\n\t.reg .pred P;\n\t"
        "LW_%=:\n\t"
        "mbarrier.try_wait.parity.acquire.cluster.shared::cta.b64 P, [%0], %1, 0x989680;\n\t"
        "@P bra.uni LD_%=;\n\t"
        "bra.uni LW_%=;\n\t"
        "LD_%=:\n\t}"
        :: "r"(a), "r"(parity) : "memory");
}
__device__ __forceinline__ void st_async_pre(unsigned ra, unsigned rb, unsigned val) {
    asm volatile(
        "st.async.shared::cluster.mbarrier::complete_tx::bytes.b32 [%0], %1, [%2];"
        :: "r"(ra), "r"(val), "r"(rb) : "memory");
}
__device__ __forceinline__ void cp_async16(unsigned dst, const void* src) {
    asm volatile("cp.async.cg.shared.global [%0], [%1], 16;"
                 :: "r"(dst), "l"(src) : "memory");
}
__device__ __forceinline__ void cp_commit() {
    asm volatile("cp.async.commit_group;" ::: "memory");
}
template <int N>
__device__ __forceinline__ void cp_wait() {
    asm volatile("cp.async.wait_group %0;" :: "n"(N) : "memory");
}
__device__ __forceinline__ void mma_bf16(float c[4], const unsigned a[4],
                                         unsigned b0, unsigned b1) {
    asm volatile(
        "mma.sync.aligned.m16n8k16.row.col.f32.bf16.bf16.f32 "
        "{%0,%1,%2,%3}, {%4,%5,%6,%7}, {%8,%9}, {%0,%1,%2,%3};"
        : "+f"(c[0]), "+f"(c[1]), "+f"(c[2]), "+f"(c[3])
        : "r"(a[0]), "r"(a[1]), "r"(a[2]), "r"(a[3]), "r"(b0), "r"(b1));
}
__device__ __forceinline__ void ldm_x4(unsigned& r0, unsigned& r1,
                                       unsigned& r2, unsigned& r3, unsigned addr) {
    asm volatile("ldmatrix.sync.aligned.m8n8.x4.shared.b16 {%0,%1,%2,%3}, [%4];"
                 : "=r"(r0), "=r"(r1), "=r"(r2), "=r"(r3) : "r"(addr));
}

// ---------------------------------------------------------------------------
// Transpose + bf16 hi/lo split conversion
// ---------------------------------------------------------------------------
__device__ __forceinline__ void convert_body(const float* __restrict__ src,
                                             __nv_bfloat16* __restrict__ dhi,
                                             __nv_bfloat16* __restrict__ dlo,
                                             int K, int N)
{
    __shared__ float tile[32][33];
    int x = threadIdx.x & 31, y = threadIdx.x >> 5;
    int k0 = blockIdx.x * 32, n0 = blockIdx.y * 32;
#pragma unroll
    for (int j = 0; j < 4; j++) {
        int k = k0 + y + j * 8;
        float v = 0.f;
        if (k < K) v = src[(size_t)k * N + n0 + x];
        tile[y + j * 8][x] = v;
    }
    __syncthreads();
#pragma unroll
    for (int j = 0; j < 4; j++) {
        int n = n0 + y + j * 8;
        int k = k0 + x;
        float v = tile[x][y + j * 8];
        __nv_bfloat16 hi = __float2bfloat16(v);
        float r = v - __bfloat162float(hi);
        __nv_bfloat16 lo = __float2bfloat16(r);
        dhi[(size_t)n * KPAD + k] = hi;
        dlo[(size_t)n * KPAD + k] = lo;
    }
}
__global__ void __launch_bounds__(256)
convert_H_kernel(const float* __restrict__ H)
{ convert_body(H, g_HhiT, g_HloT, N_CODES, T_STEPS); }
__global__ void __launch_bounds__(256)
convert_X_kernel(const float* __restrict__ X)
{ convert_body(X, g_XhiT, g_XloT, N_CODES, VDIM); }

// ---------------------------------------------------------------------------
// GEMM1 via mma.sync bf16, split-bf16, smem-staged (cp.async) + ldmatrix.
//   CTA 128x64 output, 8 warps each 32x32. k-chunks of 32, double-buffered.
//   Smem rows: 32 k-elems + 8 pad = 40 elems (80 B) -> ldmatrix conflict-free.
// Layout per buffer (bytes): Ahi[0], Alo[10240], Bhi[20480], Blo[25600]; 30720.
// ---------------------------------------------------------------------------
#define G1_BUF   30720
#define G1_SMEM  (2 * G1_BUF)

__global__ void __launch_bounds__(256)
gemm1_mma_kernel()
{
    extern __shared__ char g1smem[];
    const unsigned sb = smem_u32(g1smem);
    const int tid  = threadIdx.x;
    const int w    = tid >> 5;
    const int lane = tid & 31;
    const int gid  = lane >> 2;
    const int tq   = lane & 3;
    const int lr   = lane & 7;
    const int sel  = lane >> 3;       // ldmatrix group 0..3

    const int m_base = blockIdx.x * 128;
    const int n_base = blockIdx.y * 64;
    const int m_loc  = (w & 3) * 32;
    const int n_loc  = (w >> 2) * 32;

    float acc[2][4][4];
#pragma unroll
    for (int mt = 0; mt < 2; mt++)
#pragma unroll
        for (int nt = 0; nt < 4; nt++)
#pragma unroll
            for (int i = 0; i < 4; i++) acc[mt][nt][i] = 0.0f;

    // staging: A 1024 segs (4/thread), B 512 segs (2/thread)
    auto stage = [&](int buf, int k0) {
        unsigned base = sb + buf * G1_BUF;
#pragma unroll
        for (int j = 0; j < 4; j++) {
            int flat = (j << 8) + tid;
            int seg  = flat & 3;
            int row  = (flat >> 2) & 127;
            int half = flat >> 9;
            const __nv_bfloat16* src = (half ? g_HloT : g_HhiT)
                + (size_t)(m_base + row) * KPAD + k0 + (seg << 3);
            cp_async16(base + half * 10240 + row * 80 + (seg << 4), src);
        }
#pragma unroll
        for (int j = 0; j < 2; j++) {
            int flat = (j << 8) + tid;
            int seg  = flat & 3;
            int row  = (flat >> 2) & 63;
            int half = flat >> 8;
            const __nv_bfloat16* src = (half ? g_XloT : g_XhiT)
                + (size_t)(n_base + row) * KPAD + k0 + (seg << 3);
            cp_async16(base + 20480 + half * 5120 + row * 80 + (seg << 4), src);
        }
        cp_commit();
    };

    const int nch = KPAD / 32;    // 153
    stage(0, 0);
    for (int ch = 0; ch < nch; ch++) {
        const int buf = ch & 1;
        if (ch + 1 < nch) {
            stage(buf ^ 1, (ch + 1) * 32);
            cp_wait<1>();
        } else {
            cp_wait<0>();
        }
        __syncthreads();

        const unsigned base = sb + buf * G1_BUF;
        // B fragments for whole chunk: x4 covers k 0..31 (4 n8k8 matrices)
        unsigned bh[4][4], bl[4][4];
#pragma unroll
        for (int nt = 0; nt < 4; nt++) {
            unsigned ba = base + 20480 + (n_loc + nt * 8 + lr) * 80 + (sel << 4);
            ldm_x4(bh[nt][0], bh[nt][1], bh[nt][2], bh[nt][3], ba);
            ldm_x4(bl[nt][0], bl[nt][1], bl[nt][2], bl[nt][3], ba + 5120);
        }
#pragma unroll
        for (int s = 0; s < 2; s++) {
            const int ks = s << 4;
            unsigned ahi[2][4], alo[2][4];
#pragma unroll
            for (int mt = 0; mt < 2; mt++) {
                unsigned aa = base
                    + (m_loc + mt * 16 + lr + ((sel & 1) << 3)) * 80
                    + ((ks + ((sel >> 1) << 3)) << 1);
                ldm_x4(ahi[mt][0], ahi[mt][1], ahi[mt][2], ahi[mt][3], aa);
                ldm_x4(alo[mt][0], alo[mt][1], alo[mt][2], alo[mt][3], aa + 10240);
            }
#pragma unroll
            for (int nt = 0; nt < 4; nt++) {
#pragma unroll
                for (int mt = 0; mt < 2; mt++) {
                    mma_bf16(acc[mt][nt], ahi[mt], bh[nt][2 * s], bh[nt][2 * s + 1]);
                    mma_bf16(acc[mt][nt], ahi[mt], bl[nt][2 * s], bl[nt][2 * s + 1]);
                    mma_bf16(acc[mt][nt], alo[mt], bh[nt][2 * s], bh[nt][2 * s + 1]);
                }
            }
        }
        __syncthreads();
    }

    // store (validated mapping)
#pragma unroll
    for (int mt = 0; mt < 2; mt++) {
        int row = m_base + m_loc + mt * 16 + gid;
#pragma unroll
        for (int nt = 0; nt < 4; nt++) {
            int col = n_base + n_loc + nt * 8 + 2 * tq;
            *(float2*)(g_visit + (size_t)row * VDIM + col) =
                make_float2(acc[mt][nt][0], acc[mt][nt][1]);
            *(float2*)(g_visit + (size_t)(row + 8) * VDIM + col) =
                make_float2(acc[mt][nt][2], acc[mt][nt][3]);
        }
    }
}

// ---------------------------------------------------------------------------
// GEMM2 (R13, validated)
// ---------------------------------------------------------------------------
__global__ void __launch_bounds__(256)
gemm2_kernel(const float* __restrict__ Wih, const float* __restrict__ bih)
{
    __shared__ float As[16 * 128];
    __shared__ float Bs[16 * 64];
    const int tid = threadIdx.x;
    const int t0 = blockIdx.x * 128;
    const int g0 = blockIdx.y * 64;
    const int tx = tid & 15;
    const int ty = tid >> 4;

    const int s_tt0 = tid >> 2;
    const int s_kk  = (tid & 3) << 2;
    const int s_gg  = tid >> 2;

    ull acc2[4][4];
#pragma unroll
    for (int mp = 0; mp < 4; mp++)
#pragma unroll
        for (int n = 0; n < 4; n++) acc2[mp][n] = 0ull;

    float4 ra0, ra1, rbv;
    auto load_tile = [&](int k0) {
        ra0 = *(const float4*)(g_visit + (size_t)(t0 + s_tt0) * VDIM + k0 + s_kk);
        ra1 = *(const float4*)(g_visit + (size_t)(t0 + s_tt0 + 64) * VDIM + k0 + s_kk);
        rbv = *(const float4*)(Wih + (size_t)(g0 + s_gg) * VDIM + k0 + s_kk);
    };
    auto store_tile = [&]() {
        As[(s_kk + 0) * 128 + s_tt0] = ra0.x;
        As[(s_kk + 1) * 128 + s_tt0] = ra0.y;
        As[(s_kk + 2) * 128 + s_tt0] = ra0.z;
        As[(s_kk + 3) * 128 + s_tt0] = ra0.w;
        As[(s_kk + 0) * 128 + s_tt0 + 64] = ra1.x;
        As[(s_kk + 1) * 128 + s_tt0 + 64] = ra1.y;
        As[(s_kk + 2) * 128 + s_tt0 + 64] = ra1.z;
        As[(s_kk + 3) * 128 + s_tt0 + 64] = ra1.w;
        Bs[(s_kk + 0) * 64 + s_gg] = rbv.x;
        Bs[(s_kk + 1) * 64 + s_gg] = rbv.y;
        Bs[(s_kk + 2) * 64 + s_gg] = rbv.z;
        Bs[(s_kk + 3) * 64 + s_gg] = rbv.w;
    };

    load_tile(0);
    for (int k0 = 0; k0 < VDIM; k0 += 16) {
        store_tile();
        __syncthreads();
        if (k0 + 16 < VDIM) load_tile(k0 + 16);
#pragma unroll
        for (int kk = 0; kk < 16; kk++) {
            const longlong2* ap = (const longlong2*)(As + (kk << 7) + (ty << 3));
            longlong2 a01 = ap[0];
            longlong2 a23 = ap[1];
            ull am[4] = {(ull)a01.x, (ull)a01.y, (ull)a23.x, (ull)a23.y};
            float4 b = *(const float4*)(Bs + (kk << 6) + (tx << 2));
            ull bd[4] = {pk2dup(b.x), pk2dup(b.y), pk2dup(b.z), pk2dup(b.w)};
#pragma unroll
            for (int mp = 0; mp < 4; mp++)
#pragma unroll
                for (int n = 0; n < 4; n++)
                    fma2(acc2[mp][n], am[mp], bd[n]);
        }
        __syncthreads();
    }
    float4 bv = *(const float4*)(bih + g0 + (tx << 2));
#pragma unroll
    for (int mp = 0; mp < 4; mp++) {
        float2 c0 = upk2(acc2[mp][0]);
        float2 c1 = upk2(acc2[mp][1]);
        float2 c2 = upk2(acc2[mp][2]);
        float2 c3 = upk2(acc2[mp][3]);
        size_t r0 = (size_t)(t0 + (ty << 3) + 2 * mp) * G3 + g0 + (tx << 2);
        *(float4*)(g_gi + r0)      = make_float4(c0.x + bv.x, c1.x + bv.y, c2.x + bv.z, c3.x + bv.w);
        *(float4*)(g_gi + r0 + G3) = make_float4(c0.y + bv.x, c1.y + bv.y, c2.y + bv.z, c3.y + bv.w);
    }
}

// ---------------------------------------------------------------------------
// GRU scan — frozen R10 build (best validated).
// ---------------------------------------------------------------------------
#define SCAN_THREADS 256

__global__ void __launch_bounds__(SCAN_THREADS, 1)
scan_kernel(const float* __restrict__ Whh, const float* __restrict__ bhh)
{
    __shared__ float  hT[2 * HD];
    __shared__ ull    mbar[2];

    const int tid  = threadIdx.x;
    const int lane = tid & 31;
    const int w    = tid >> 5;
    const int cta  = blockIdx.x;
    const int c4   = lane & 15;
    const int rh   = lane >> 4;

    const int ui    = ((lane & 1) << 1) | rh;
    const int q     = (lane >> 1) & 7;
    const int ul    = (w << 2) + ui;
    const int u_gbl = (cta << 5) + ul;

    ull wreg[6][16];
#pragma unroll
    for (int g = 0; g < 6; g++) {
        int grow = ((g >> 1) << 9) + (cta << 5) + (w << 2) + ((g & 1) << 1) + rh;
        const ull* src = (const ull*)(Whh + (size_t)grow * HD + (c4 << 5));
#pragma unroll
        for (int k = 0; k < 16; k++) wreg[g][k] = src[k];
    }
    const float br = bhh[u_gbl];
    const float bz = bhh[HD + u_gbl];
    const float bn = bhh[2 * HD + u_gbl];

    for (int i = tid; i < HD; i += SCAN_THREADS) hT[i] = 0.0f;
    if (tid == 0) { mbar_init(smem_u32(&mbar[0]), 1); mbar_init(smem_u32(&mbar[1]), 1); }
    __syncthreads();
    cluster_sync_all();

    const int hoffb = ((ul >> 2) << 6) + (cta << 2) + (ul & 3);
    unsigned rdata[2][2], rbar[2][2];
#pragma unroll
    for (int b = 0; b < 2; b++) {
        unsigned ld = smem_u32(&hT[(b << 9) + hoffb]);
        unsigned lm = smem_u32(&mbar[b]);
#pragma unroll
        for (int r = 0; r < 2; r++) {
            rdata[b][r] = mapa_u32(ld, (q << 1) + r);
            rbar[b][r]  = mapa_u32(lm, (q << 1) + r);
        }
    }

    const float* gp_cur = g_gi + u_gbl;
    float gir = __ldg(gp_cur);
    float giz = __ldg(gp_cur + HD);
    float gin = __ldg(gp_cur + 2 * HD);

    int ph0 = 0, ph1 = 0;
    const bool b0 = (lane & 1);
    for (int t = 0; t < T_STEPS; t++) {
        const int cb = t & 1;
        const int nb = cb ^ 1;

        if (tid == 0) mbar_expect(smem_u32(&mbar[nb]), 2048u);

        const float* gp_n = (t + 1 < T_STEPS) ? (gp_cur + G3) : gp_cur;
        float girn = __ldg(gp_n);
        float gizn = __ldg(gp_n + HD);
        float ginn = __ldg(gp_n + 2 * HD);
        gp_cur = gp_n;

        ull h2[16];
        {
            const longlong2* hp = (const longlong2*)(hT + (cb << 9));
#pragma unroll
            for (int j = 0; j < 8; j++) {
                longlong2 qv = hp[(j << 4) + c4];
                h2[2 * j]     = (ull)qv.x;
                h2[2 * j + 1] = (ull)qv.y;
            }
        }
        float hold = hT[(cb << 9) + hoffb];

        float accs[6];
#pragma unroll
        for (int g = 0; g < 6; g++) {
            ull a = 0ull;
#pragma unroll
            for (int k = 0; k < 16; k++) fma2(a, wreg[g][k], h2[k]);
            float2 u2 = upk2(a);
            accs[g] = u2.x + u2.y;
        }

#pragma unroll
        for (int d = 8; d > 1; d >>= 1)
#pragma unroll
            for (int g = 0; g < 6; g++)
                accs[g] += __shfl_xor_sync(0xffffffffu, accs[g], d);

        float v0 = b0 ? accs[0] : accs[1];
        float v1 = b0 ? accs[2] : accs[3];
        float v2 = b0 ? accs[4] : accs[5];
        float pr = (b0 ? accs[1] : accs[0]) + __shfl_xor_sync(0xffffffffu, v0, 1);
        float pz = (b0 ? accs[3] : accs[2]) + __shfl_xor_sync(0xffffffffu, v1, 1);
        float pn = (b0 ? accs[5] : accs[4]) + __shfl_xor_sync(0xffffffffu, v2, 1);

        float rg = fmaf(0.5f, tanh_fast(0.5f * (gir + pr + br)), 0.5f);
        float zg = fmaf(0.5f, tanh_fast(0.5f * (giz + pz + bz)), 0.5f);
        float ng = tanh_fast(fmaf(rg, pn + bn, gin));
        float hnew = fmaf(zg, hold - ng, ng);

        if (q == 0) g_hs[(size_t)t * HD + u_gbl] = hnew;

        unsigned hv = __float_as_uint(hnew);
        st_async_pre(rdata[nb][0], rbar[nb][0], hv);
        st_async_pre(rdata[nb][1], rbar[nb][1], hv);

        gir = girn; giz = gizn; gin = ginn;

        unsigned par = nb ? (unsigned)ph1 : (unsigned)ph0;
        mbar_wait(smem_u32(&mbar[nb]), par);
        if (nb) ph1 ^= 1; else ph0 ^= 1;
    }
    cluster_sync_all();
}

// ---------------------------------------------------------------------------
// Attention pooling (R13, validated)
// ---------------------------------------------------------------------------
__global__ void __launch_bounds__(256)
att_logits_kernel(const float* __restrict__ watt)
{
    int t = blockIdx.x * 8 + (threadIdx.x >> 5);
    int lane = threadIdx.x & 31;
    const float4* hp = (const float4*)(g_hs + (size_t)t * HD);
    const float4* wp = (const float4*)watt;
    float acc = 0.f;
#pragma unroll
    for (int j = 0; j < 4; j++) {
        float4 h4 = __ldg(hp + lane + (j << 5));
        float4 w4 = __ldg(wp + lane + (j << 5));
        acc += h4.x * w4.x + h4.y * w4.y + h4.z * w4.z + h4.w * w4.w;
    }
    acc += __shfl_xor_sync(0xffffffffu, acc, 16);
    acc += __shfl_xor_sync(0xffffffffu, acc, 8);
    acc += __shfl_xor_sync(0xffffffffu, acc, 4);
    acc += __shfl_xor_sync(0xffffffffu, acc, 2);
    acc += __shfl_xor_sync(0xffffffffu, acc, 1);
    if (lane == 0) g_logits[t] = acc;
}

__global__ void __launch_bounds__(1024)
att_softmax_kernel()
{
    __shared__ float red[1024];
    int tid = threadIdx.x;
    float l[4];
    float mx = -1e30f;
#pragma unroll
    for (int i = 0; i < 4; i++) {
        l[i] = g_logits[tid + (i << 10)];
        mx = fmaxf(mx, l[i]);
    }
    red[tid] = mx;
    __syncthreads();
    for (int s = 512; s > 0; s >>= 1) {
        if (tid < s) red[tid] = fmaxf(red[tid], red[tid + s]);
        __syncthreads();
    }
    mx = red[0];
    __syncthreads();
    float e[4];
    float se = 0.f;
#pragma unroll
    for (int i = 0; i < 4; i++) {
        e[i] = __expf(l[i] - mx);
        se += e[i];
    }
    red[tid] = se;
    __syncthreads();
    for (int s = 512; s > 0; s >>= 1) {
        if (tid < s) red[tid] += red[tid + s];
        __syncthreads();
    }
    float inv = 1.0f / red[0];
#pragma unroll
    for (int i = 0; i < 4; i++)
        g_alpha[tid + (i << 10)] = e[i] * inv;
}

__global__ void __launch_bounds__(512)
att_out_kernel()
{
    int b = blockIdx.x;
    int d = threadIdx.x;
    float acc = 0.f;
#pragma unroll 4
    for (int i = 0; i < 32; i++) {
        int t = b * 32 + i;
        acc += g_alpha[t] * g_hs[(size_t)t * HD + d];
    }
    g_part[b * HD + d] = acc;
}

__global__ void __launch_bounds__(512)
att_final_kernel(float* __restrict__ out)
{
    int d = threadIdx.x;
    float acc = 0.f;
#pragma unroll
    for (int b = 0; b < 128; b++)
        acc += g_part[b * HD + d];
    out[d] = acc;
}

// ---------------------------------------------------------------------------
// Launch — single stream (proven structure)
// ---------------------------------------------------------------------------
extern "C" void kernel_launch(void* const* d_in, const int* in_sizes, int n_in,
                              void* d_out, int out_size)
{
    const float* H    = (const float*)d_in[0];
    // d_in[1] = TE (unused by reference)
    const float* X    = (const float*)d_in[2];
    const float* Wih  = (const float*)d_in[3];
    const float* Whh  = (const float*)d_in[4];
    const float* bih  = (const float*)d_in[5];
    const float* bhh  = (const float*)d_in[6];
    const float* watt = (const float*)d_in[7];
    float* out = (float*)d_out;

    convert_H_kernel<<<dim3(153, 128), 256>>>(H);
    convert_X_kernel<<<dim3(153, 16), 256>>>(X);

    cudaFuncSetAttribute(gemm1_mma_kernel,
                         cudaFuncAttributeMaxDynamicSharedMemorySize, G1_SMEM);
    gemm1_mma_kernel<<<dim3(32, 8), 256, G1_SMEM>>>();

    gemm2_kernel<<<dim3(32, 24), 256>>>(Wih, bih);

    cudaFuncSetAttribute(scan_kernel,
                         cudaFuncAttributeNonPortableClusterSizeAllowed, 1);

    cudaLaunchConfig_t cfg = {};
    cfg.gridDim = dim3(16, 1, 1);
    cfg.blockDim = dim3(SCAN_THREADS, 1, 1);
    cfg.dynamicSmemBytes = 0;
    cfg.stream = 0;
    cudaLaunchAttribute attr[1];
    attr[0].id = cudaLaunchAttributeClusterDimension;
    attr[0].val.clusterDim.x = 16;
    attr[0].val.clusterDim.y = 1;
    attr[0].val.clusterDim.z = 1;
    cfg.attrs = attr;
    cfg.numAttrs = 1;
    cudaLaunchKernelEx(&cfg, scan_kernel, Whh, bhh);

    att_logits_kernel<<<512, 256>>>(watt);
    att_softmax_kernel<<<1, 1024>>>();
    att_out_kernel<<<128, 512>>>();
    att_final_kernel<<<1, 512>>>(out);
}